// round 15
// baseline (speedup 1.0000x reference)
#include <cuda_runtime.h>
#include <cstdint>

#define TT    101
#define W0F   44.0f
#define NTHR  320
#define WPC   (NTHR / 32)

// ---- dynamic smem layout (bytes) ----
#define BF_OFF    0                   // W2 f16 frags [ntp][kt][g][tig] uint4: 32 KB
#define P1_OFF    32768               // float4[128]: (44*W1x, 44*W1y, 44*b1, 0)
#define WB_OFF    (P1_OFF + 2048)     // float4[128]: (W3x, W3y, 44*b2, 0)
#define DTS_OFF   (WB_OFF + 2048)     // float[100]
#define B3_OFF    (DTS_OFF + 512)     // float[2]
#define SMEM_TOTAL (B3_OFF + 16)

// pack two f32 -> f16x2, first arg in the LOW half
static __device__ __forceinline__ uint32_t h2(float lo, float hi) {
    uint32_t r;
    asm("cvt.rn.f16x2.f32 %0, %1, %2;" : "=r"(r) : "f"(hi), "f"(lo));
    return r;
}

static __device__ __forceinline__ void mma16(float* d, const uint32_t* a,
                                             uint32_t b0, uint32_t b1) {
    asm volatile(
        "mma.sync.aligned.m16n8k16.row.col.f32.f16.f16.f32 "
        "{%0,%1,%2,%3}, {%4,%5,%6,%7}, {%8,%9}, {%0,%1,%2,%3};"
        : "+f"(d[0]), "+f"(d[1]), "+f"(d[2]), "+f"(d[3])
        : "r"(a[0]), "r"(a[1]), "r"(a[2]), "r"(a[3]), "r"(b0), "r"(b1));
}

// One SIREN vector-field eval for this warp's 32 points (lane l owns point l).
// A-fragments hoisted once (64 regs). GEMM runs in TWO n-halves with acc[64]:
// 16 independent depth-8 MMA chains per half (vs R12's 8 — the chain-count
// threshold), registers ~175 -> 10 warps/SM for cross-warp pipe overlap.
__device__ __noinline__ void feval(float px, float py, const char* sm,
                                   int lane, float b3x, float b3y,
                                   float& fx, float& fy) {
    const int g = lane >> 2, tig = lane & 3;

    // coords of the 4 rows (8j+g) whose fragment slots this lane owns
    float rx[4], ry[4];
#pragma unroll
    for (int j = 0; j < 4; j++) {
        rx[j] = __shfl_sync(0xffffffffu, px, 8 * j + g);
        ry[j] = __shfl_sync(0xffffffffu, py, 8 * j + g);
    }

    const float4* P1 = reinterpret_cast<const float4*>(sm + P1_OFF);
    const float4* WB = reinterpret_cast<const float4*>(sm + WB_OFF);
    const uint4* BF = reinterpret_cast<const uint4*>(sm + BF_OFF);

    // ---- layer 1: all A fragments (64 regs), rows 8j+g, k-chunks of 16 ----
    uint32_t A[8][8];
#pragma unroll
    for (int kt = 0; kt < 8; kt++) {
        const int c0 = 16 * kt + 2 * tig;
        float4 pA = P1[c0], pB = P1[c0 + 1], pC = P1[c0 + 8], pD = P1[c0 + 9];
#pragma unroll
        for (int j = 0; j < 4; j++) {
            float sA = __sinf(fmaf(rx[j], pA.x, fmaf(ry[j], pA.y, pA.z)));
            float sB = __sinf(fmaf(rx[j], pB.x, fmaf(ry[j], pB.y, pB.z)));
            float sC = __sinf(fmaf(rx[j], pC.x, fmaf(ry[j], pC.y, pC.z)));
            float sD = __sinf(fmaf(rx[j], pD.x, fmaf(ry[j], pD.y, pD.z)));
            const int m = j >> 1, rs = j & 1;
            A[kt][m * 4 + rs]     = h2(sA, sB);   // low-k pair
            A[kt][m * 4 + rs + 2] = h2(sC, sD);   // high-k pair
        }
    }

    // ---- layers 2+3 in two n-halves of 64 columns each ----
    float ps[8];
#pragma unroll
    for (int i = 0; i < 8; i++) ps[i] = 0.0f;

#pragma unroll
    for (int h = 0; h < 2; h++) {
        float acc[64];  // [j(4)][tile(2)][m(2)][4]: 16 depth-8 chains
#pragma unroll
        for (int i = 0; i < 64; i++) acc[i] = 0.0f;

#pragma unroll
        for (int kt = 0; kt < 8; kt++) {
#pragma unroll
            for (int j = 0; j < 4; j++) {
                const int ntp = 4 * h + j;
                uint4 b = BF[(ntp * 8 + kt) * 32 + g * 4 + tig];
                mma16(acc + j * 16 + 0,  A[kt],     b.x, b.y);  // t0, rows 0-15
                mma16(acc + j * 16 + 4,  A[kt] + 4, b.x, b.y);  // t0, rows 16-31
                mma16(acc + j * 16 + 8,  A[kt],     b.z, b.w);  // t1, rows 0-15
                mma16(acc + j * 16 + 12, A[kt] + 4, b.z, b.w);  // t1, rows 16-31
            }
        }
        // epilogue for this half's 64 columns
#pragma unroll
        for (int j = 0; j < 4; j++) {
#pragma unroll
            for (int tile = 0; tile < 2; tile++) {
                const int nt8 = (4 * h + j) * 2 + tile;  // n8-tile index 0..15
                float4 w0 = WB[8 * nt8 + 2 * tig];
                float4 w1 = WB[8 * nt8 + 2 * tig + 1];
#pragma unroll
                for (int m = 0; m < 2; m++) {
                    const float* d = acc + j * 16 + tile * 8 + m * 4;
                    float h00 = __sinf(fmaf(W0F, d[0], w0.z));  // row g
                    float h01 = __sinf(fmaf(W0F, d[1], w1.z));
                    float h10 = __sinf(fmaf(W0F, d[2], w0.z));  // row g+8
                    float h11 = __sinf(fmaf(W0F, d[3], w1.z));
                    ps[m * 4 + 0] = fmaf(h00, w0.x, fmaf(h01, w1.x, ps[m * 4 + 0]));
                    ps[m * 4 + 1] = fmaf(h00, w0.y, fmaf(h01, w1.y, ps[m * 4 + 1]));
                    ps[m * 4 + 2] = fmaf(h10, w0.x, fmaf(h11, w1.x, ps[m * 4 + 2]));
                    ps[m * 4 + 3] = fmaf(h10, w0.y, fmaf(h11, w1.y, ps[m * 4 + 3]));
                }
            }
        }
    }

    // reduce across the 4 lanes of each thread-group (lane bits 0,1)
#pragma unroll
    for (int d = 1; d <= 2; d <<= 1)
#pragma unroll
        for (int i = 0; i < 8; i++)
            ps[i] += __shfl_xor_sync(0xffffffffu, ps[i], d);

    // route row r = 8*s + g back to owner lane r (src lane = (r&7)*4);
    // ps index = 2*s + comp where s = 2m+h_row, row = 8s+g
    const int src = (lane & 7) * 4;
    float rx0 = __shfl_sync(0xffffffffu, ps[0], src);
    float ry0 = __shfl_sync(0xffffffffu, ps[1], src);
    float rx1 = __shfl_sync(0xffffffffu, ps[2], src);
    float ry1 = __shfl_sync(0xffffffffu, ps[3], src);
    float rx2 = __shfl_sync(0xffffffffu, ps[4], src);
    float ry2 = __shfl_sync(0xffffffffu, ps[5], src);
    float rx3 = __shfl_sync(0xffffffffu, ps[6], src);
    float ry3 = __shfl_sync(0xffffffffu, ps[7], src);
    const int s = lane >> 3;
    fx = b3x + ((s == 0) ? rx0 : (s == 1) ? rx1 : (s == 2) ? rx2 : rx3);
    fy = b3y + ((s == 0) ? ry0 : (s == 1) ? ry1 : (s == 2) ? ry2 : ry3);
}

extern "C" __global__ void __launch_bounds__(NTHR, 1)
node_hmma(const float* __restrict__ t, const float* __restrict__ x0,
          const float* __restrict__ W1, const float* __restrict__ b1,
          const float* __restrict__ W2, const float* __restrict__ b2,
          const float* __restrict__ W3, const float* __restrict__ b3g,
          float* __restrict__ out, int N) {
    extern __shared__ char sm[];
    const int tid = threadIdx.x;
    const int lane = tid & 31;

    // ---- stage W2 as f16 fragment uint4s: [ntp][kt][g][tig] ----
    // .x/.y = B-frag (b0,b1) for n0 = 16ntp+g; .z/.w = same for n1 = n0+8
    for (int idx = tid; idx < 2048; idx += NTHR) {
        int tg = idx & 3, g = (idx >> 2) & 7, kt = (idx >> 5) & 7, ntp = idx >> 8;
        int n0 = 16 * ntp + g, n1 = n0 + 8;
        int k0 = 16 * kt + 2 * tg;
        uint4 v;
        v.x = h2(W2[k0 * 128 + n0],       W2[(k0 + 1) * 128 + n0]);
        v.y = h2(W2[(k0 + 8) * 128 + n0], W2[(k0 + 9) * 128 + n0]);
        v.z = h2(W2[k0 * 128 + n1],       W2[(k0 + 1) * 128 + n1]);
        v.w = h2(W2[(k0 + 8) * 128 + n1], W2[(k0 + 9) * 128 + n1]);
        reinterpret_cast<uint4*>(sm + BF_OFF)[idx] = v;
    }
    for (int k = tid; k < 128; k += NTHR) {
        reinterpret_cast<float4*>(sm + P1_OFF)[k] =
            make_float4(W0F * W1[k], W0F * W1[128 + k], W0F * b1[k], 0.0f);
        reinterpret_cast<float4*>(sm + WB_OFF)[k] =
            make_float4(W3[2 * k], W3[2 * k + 1], W0F * b2[k], 0.0f);
    }
    for (int s = tid; s < TT - 1; s += NTHR)
        reinterpret_cast<float*>(sm + DTS_OFF)[s] = t[s + 1] - t[s];
    if (tid < 2) reinterpret_cast<float*>(sm + B3_OFF)[tid] = b3g[tid];
    __syncthreads();  // only CTA-wide sync; warps independent afterwards

    const float b3x = reinterpret_cast<const float*>(sm + B3_OFF)[0];
    const float b3y = reinterpret_cast<const float*>(sm + B3_OFF)[1];

    const int gid = blockIdx.x * NTHR + tid;
    const bool live = gid < N;
    float2 y = live ? reinterpret_cast<const float2*>(x0)[gid]
                    : make_float2(0.0f, 0.0f);
    float2* outv = reinterpret_cast<float2*>(out);
    if (live) outv[gid] = y;  // t = 0 row

    const float third = 1.0f / 3.0f;
#pragma unroll 1
    for (int s = 0; s < TT - 1; s++) {
        float dt = reinterpret_cast<const float*>(sm + DTS_OFF)[s];
        float k1x, k1y, k2x, k2y, k3x, k3y, k4x, k4y;
        // torchdiffeq rk4_alt (3/8-rule)
        feval(y.x, y.y, sm, lane, b3x, b3y, k1x, k1y);
        feval(y.x + dt * k1x * third, y.y + dt * k1y * third,
              sm, lane, b3x, b3y, k2x, k2y);
        feval(y.x + dt * (k2x - k1x * third), y.y + dt * (k2y - k1y * third),
              sm, lane, b3x, b3y, k3x, k3y);
        feval(y.x + dt * (k1x - k2x + k3x), y.y + dt * (k1y - k2y + k3y),
              sm, lane, b3x, b3y, k4x, k4y);
        y.x = y.x + (k1x + 3.0f * (k2x + k3x) + k4x) * dt * 0.125f;
        y.y = y.y + (k1y + 3.0f * (k2y + k3y) + k4y) * dt * 0.125f;
        if (live) outv[(size_t)(s + 1) * N + gid] = y;
    }
}

extern "C" void kernel_launch(void* const* d_in, const int* in_sizes, int n_in,
                              void* d_out, int out_size) {
    const float* t  = (const float*)d_in[0];
    const float* x0 = (const float*)d_in[1];
    const float* W1 = (const float*)d_in[2];
    const float* b1 = (const float*)d_in[3];
    const float* W2 = (const float*)d_in[4];
    const float* b2 = (const float*)d_in[5];
    const float* W3 = (const float*)d_in[6];
    const float* b3 = (const float*)d_in[7];
    int N = in_sizes[1] / 2;

    cudaFuncSetAttribute(node_hmma,
                         cudaFuncAttributeMaxDynamicSharedMemorySize, SMEM_TOTAL);
    int grid = (N + NTHR - 1) / NTHR;
    node_hmma<<<grid, NTHR, SMEM_TOTAL>>>(t, x0, W1, b1, W2, b2, W3, b3,
                                          (float*)d_out, N);
}

// round 16
// speedup vs baseline: 1.0267x; 1.0267x over previous
#include <cuda_runtime.h>
#include <cuda_fp16.h>
#include <cstdint>

#define TT    101
#define W0F   44.0f
#define NTHR  320

// ---- dynamic smem layout (bytes) ----
#define BF_OFF    0                   // W2 f16 frags [ntp][kt][g][tig] uint4: 32 KB
#define P1_OFF    32768               // float4[128]: (44*W1x, 44*W1y, 44*b1, 0)
#define WB_OFF    (P1_OFF + 2048)     // float4[128]: (W3x, W3y, 44*b2, 0)
#define DTS_OFF   (WB_OFF + 2048)     // float[100]
#define B3_OFF    (DTS_OFF + 512)     // float[2]
#define SMEM_TOTAL (B3_OFF + 16)

// pack two f32 -> f16x2, first arg in the LOW half
static __device__ __forceinline__ uint32_t h2(float lo, float hi) {
    uint32_t r;
    asm("cvt.rn.f16x2.f32 %0, %1, %2;" : "=r"(r) : "f"(hi), "f"(lo));
    return r;
}

// m16n8k16 with fp16 accumulators: D/C are 2 packed f16x2 regs.
// c[0] = {row g:   col 2tig (lo), col 2tig+1 (hi)}
// c[1] = {row g+8: col 2tig (lo), col 2tig+1 (hi)}
static __device__ __forceinline__ void mma16h(uint32_t* c, const uint32_t* a,
                                              uint32_t b0, uint32_t b1) {
    asm volatile(
        "mma.sync.aligned.m16n8k16.row.col.f16.f16.f16.f16 "
        "{%0,%1}, {%2,%3,%4,%5}, {%6,%7}, {%0,%1};"
        : "+r"(c[0]), "+r"(c[1])
        : "r"(a[0]), "r"(a[1]), "r"(a[2]), "r"(a[3]), "r"(b0), "r"(b1));
}

// One SIREN vector-field eval for this warp's 32 points (lane l owns point l).
// R9 structure: single pass over 32 independent depth-8 MMA chains, layer-1
// sins computed per-kt inside the loop. fp16 accumulators halve acc registers
// (64 vs 128) -> 10 warps/SM. Safe because |D|~0.023 (SIREN's 1/w0 scaling).
__device__ __noinline__ void feval(float px, float py, const char* sm,
                                   int lane, float b3x, float b3y,
                                   float& fx, float& fy) {
    const int g = lane >> 2, tig = lane & 3;

    // coords of the 4 rows (8j+g) whose fragment slots this lane owns
    float rx[4], ry[4];
#pragma unroll
    for (int j = 0; j < 4; j++) {
        rx[j] = __shfl_sync(0xffffffffu, px, 8 * j + g);
        ry[j] = __shfl_sync(0xffffffffu, py, 8 * j + g);
    }

    uint32_t acch[64];  // 32 n8-tiles x 2 packed f16x2 regs
#pragma unroll
    for (int i = 0; i < 64; i++) acch[i] = 0u;

    const float4* P1 = reinterpret_cast<const float4*>(sm + P1_OFF);
    const uint4* BF = reinterpret_cast<const uint4*>(sm + BF_OFF);

#pragma unroll
    for (int kt = 0; kt < 8; kt++) {
        const int c0 = 16 * kt + 2 * tig;
        float4 pA = P1[c0], pB = P1[c0 + 1], pC = P1[c0 + 8], pD = P1[c0 + 9];

        // A fragments: rows 8j+g, k-cols {c0,c0+1} (low pair), {c0+8,c0+9}
        uint32_t ah[8];
#pragma unroll
        for (int j = 0; j < 4; j++) {
            float sA = __sinf(fmaf(rx[j], pA.x, fmaf(ry[j], pA.y, pA.z)));
            float sB = __sinf(fmaf(rx[j], pB.x, fmaf(ry[j], pB.y, pB.z)));
            float sC = __sinf(fmaf(rx[j], pC.x, fmaf(ry[j], pC.y, pC.z)));
            float sD = __sinf(fmaf(rx[j], pD.x, fmaf(ry[j], pD.y, pD.z)));
            const int m = j >> 1, rs = j & 1;
            ah[m * 4 + rs]     = h2(sA, sB);   // low-k pair
            ah[m * 4 + rs + 2] = h2(sC, sD);   // high-k pair
        }

#pragma unroll
        for (int ntp = 0; ntp < 8; ntp++) {
            uint4 b = BF[(ntp * 8 + kt) * 32 + g * 4 + tig];
            mma16h(acch + (2 * ntp) * 2,          ah,     b.x, b.y);  // rows 0-15
            mma16h(acch + 32 + (2 * ntp) * 2,     ah + 4, b.x, b.y);  // rows 16-31
            mma16h(acch + (2 * ntp + 1) * 2,      ah,     b.z, b.w);
            mma16h(acch + 32 + (2 * ntp + 1) * 2, ah + 4, b.z, b.w);
        }
    }

    // ---- layer 3: f = sin(44*D + 44*b2) @ W3 + b3 ----
    const float4* WB = reinterpret_cast<const float4*>(sm + WB_OFF);
    float ps[8];
#pragma unroll
    for (int i = 0; i < 8; i++) ps[i] = 0.0f;
#pragma unroll
    for (int m = 0; m < 2; m++) {
#pragma unroll
        for (int nt = 0; nt < 16; nt++) {
            float4 w0 = WB[8 * nt + 2 * tig];
            float4 w1 = WB[8 * nt + 2 * tig + 1];
            float2 dlo = __half22float2(
                *reinterpret_cast<const half2*>(&acch[m * 32 + nt * 2]));
            float2 dhi = __half22float2(
                *reinterpret_cast<const half2*>(&acch[m * 32 + nt * 2 + 1]));
            float h00 = __sinf(fmaf(W0F, dlo.x, w0.z));  // row g,   col 2tig
            float h01 = __sinf(fmaf(W0F, dlo.y, w1.z));  // row g,   col 2tig+1
            float h10 = __sinf(fmaf(W0F, dhi.x, w0.z));  // row g+8
            float h11 = __sinf(fmaf(W0F, dhi.y, w1.z));
            ps[m * 4 + 0] = fmaf(h00, w0.x, fmaf(h01, w1.x, ps[m * 4 + 0]));
            ps[m * 4 + 1] = fmaf(h00, w0.y, fmaf(h01, w1.y, ps[m * 4 + 1]));
            ps[m * 4 + 2] = fmaf(h10, w0.x, fmaf(h11, w1.x, ps[m * 4 + 2]));
            ps[m * 4 + 3] = fmaf(h10, w0.y, fmaf(h11, w1.y, ps[m * 4 + 3]));
        }
    }
    // reduce across the 4 lanes of each thread-group (lane bits 0,1)
#pragma unroll
    for (int d = 1; d <= 2; d <<= 1)
#pragma unroll
        for (int i = 0; i < 8; i++)
            ps[i] += __shfl_xor_sync(0xffffffffu, ps[i], d);

    // route row r = 8*s + g back to owner lane r (src lane = (r&7)*4);
    // ps index = 2*s + comp where s = 2m+h, row = 8s+g
    const int src = (lane & 7) * 4;
    float rx0 = __shfl_sync(0xffffffffu, ps[0], src);
    float ry0 = __shfl_sync(0xffffffffu, ps[1], src);
    float rx1 = __shfl_sync(0xffffffffu, ps[2], src);
    float ry1 = __shfl_sync(0xffffffffu, ps[3], src);
    float rx2 = __shfl_sync(0xffffffffu, ps[4], src);
    float ry2 = __shfl_sync(0xffffffffu, ps[5], src);
    float rx3 = __shfl_sync(0xffffffffu, ps[6], src);
    float ry3 = __shfl_sync(0xffffffffu, ps[7], src);
    const int s = lane >> 3;
    fx = b3x + ((s == 0) ? rx0 : (s == 1) ? rx1 : (s == 2) ? rx2 : rx3);
    fy = b3y + ((s == 0) ? ry0 : (s == 1) ? ry1 : (s == 2) ? ry2 : ry3);
}

extern "C" __global__ void __launch_bounds__(NTHR, 1)
node_hmma(const float* __restrict__ t, const float* __restrict__ x0,
          const float* __restrict__ W1, const float* __restrict__ b1,
          const float* __restrict__ W2, const float* __restrict__ b2,
          const float* __restrict__ W3, const float* __restrict__ b3g,
          float* __restrict__ out, int N) {
    extern __shared__ char sm[];
    const int tid = threadIdx.x;
    const int lane = tid & 31;

    // ---- stage W2 as f16 fragment uint4s: [ntp][kt][g][tig] ----
    // .x/.y = B-frag (b0,b1) for n0 = 16ntp+g; .z/.w = same for n1 = n0+8
    for (int idx = tid; idx < 2048; idx += NTHR) {
        int tg = idx & 3, g = (idx >> 2) & 7, kt = (idx >> 5) & 7, ntp = idx >> 8;
        int n0 = 16 * ntp + g, n1 = n0 + 8;
        int k0 = 16 * kt + 2 * tg;
        uint4 v;
        v.x = h2(W2[k0 * 128 + n0],       W2[(k0 + 1) * 128 + n0]);
        v.y = h2(W2[(k0 + 8) * 128 + n0], W2[(k0 + 9) * 128 + n0]);
        v.z = h2(W2[k0 * 128 + n1],       W2[(k0 + 1) * 128 + n1]);
        v.w = h2(W2[(k0 + 8) * 128 + n1], W2[(k0 + 9) * 128 + n1]);
        reinterpret_cast<uint4*>(sm + BF_OFF)[idx] = v;
    }
    for (int k = tid; k < 128; k += NTHR) {
        reinterpret_cast<float4*>(sm + P1_OFF)[k] =
            make_float4(W0F * W1[k], W0F * W1[128 + k], W0F * b1[k], 0.0f);
        reinterpret_cast<float4*>(sm + WB_OFF)[k] =
            make_float4(W3[2 * k], W3[2 * k + 1], W0F * b2[k], 0.0f);
    }
    for (int s = tid; s < TT - 1; s += NTHR)
        reinterpret_cast<float*>(sm + DTS_OFF)[s] = t[s + 1] - t[s];
    if (tid < 2) reinterpret_cast<float*>(sm + B3_OFF)[tid] = b3g[tid];
    __syncthreads();  // only CTA-wide sync; warps independent afterwards

    const float b3x = reinterpret_cast<const float*>(sm + B3_OFF)[0];
    const float b3y = reinterpret_cast<const float*>(sm + B3_OFF)[1];

    const int gid = blockIdx.x * NTHR + tid;
    const bool live = gid < N;
    float2 y = live ? reinterpret_cast<const float2*>(x0)[gid]
                    : make_float2(0.0f, 0.0f);
    float2* outv = reinterpret_cast<float2*>(out);
    if (live) outv[gid] = y;  // t = 0 row

    const float third = 1.0f / 3.0f;
#pragma unroll 1
    for (int s = 0; s < TT - 1; s++) {
        float dt = reinterpret_cast<const float*>(sm + DTS_OFF)[s];
        float k1x, k1y, k2x, k2y, k3x, k3y, k4x, k4y;
        // torchdiffeq rk4_alt (3/8-rule)
        feval(y.x, y.y, sm, lane, b3x, b3y, k1x, k1y);
        feval(y.x + dt * k1x * third, y.y + dt * k1y * third,
              sm, lane, b3x, b3y, k2x, k2y);
        feval(y.x + dt * (k2x - k1x * third), y.y + dt * (k2y - k1y * third),
              sm, lane, b3x, b3y, k3x, k3y);
        feval(y.x + dt * (k1x - k2x + k3x), y.y + dt * (k1y - k2y + k3y),
              sm, lane, b3x, b3y, k4x, k4y);
        y.x = y.x + (k1x + 3.0f * (k2x + k3x) + k4x) * dt * 0.125f;
        y.y = y.y + (k1y + 3.0f * (k2y + k3y) + k4y) * dt * 0.125f;
        if (live) outv[(size_t)(s + 1) * N + gid] = y;
    }
}

extern "C" void kernel_launch(void* const* d_in, const int* in_sizes, int n_in,
                              void* d_out, int out_size) {
    const float* t  = (const float*)d_in[0];
    const float* x0 = (const float*)d_in[1];
    const float* W1 = (const float*)d_in[2];
    const float* b1 = (const float*)d_in[3];
    const float* W2 = (const float*)d_in[4];
    const float* b2 = (const float*)d_in[5];
    const float* W3 = (const float*)d_in[6];
    const float* b3 = (const float*)d_in[7];
    int N = in_sizes[1] / 2;

    cudaFuncSetAttribute(node_hmma,
                         cudaFuncAttributeMaxDynamicSharedMemorySize, SMEM_TOTAL);
    int grid = (N + NTHR - 1) / NTHR;
    node_hmma<<<grid, NTHR, SMEM_TOTAL>>>(t, x0, W1, b1, W2, b2, W3, b3,
                                          (float*)d_out, N);
}

// round 17
// speedup vs baseline: 1.2915x; 1.2579x over previous
#include <cuda_runtime.h>
#include <cstdint>

#define TT    101
#define W0F   44.0f
#define NTHR  256

// ---- dynamic smem layout (bytes) ----
#define BF_OFF    0                   // W2 f16 fragments [kt][ntp][g][tig] uint4: 32 KB
#define P1_OFF    32768               // float4[128]: (44*W1x, 44*W1y, 44*b1, 0)
#define WB_OFF    (P1_OFF + 2048)     // float4[128]: (W3x, W3y, 44*b2, 0)
#define DTS_OFF   (WB_OFF + 2048)     // float[100]
#define B3_OFF    (DTS_OFF + 512)     // float[2]
#define SMEM_TOTAL (B3_OFF + 16)

// pack two f32 -> f16x2, first arg in the LOW half (k-index 2tig)
static __device__ __forceinline__ uint32_t h2(float lo, float hi) {
    uint32_t r;
    asm("cvt.rn.f16x2.f32 %0, %1, %2;" : "=r"(r) : "f"(hi), "f"(lo));
    return r;
}

static __device__ __forceinline__ void mma16(float* d, const uint32_t* a,
                                             uint32_t b0, uint32_t b1) {
    asm volatile(
        "mma.sync.aligned.m16n8k16.row.col.f32.f16.f16.f32 "
        "{%0,%1,%2,%3}, {%4,%5,%6,%7}, {%8,%9}, {%0,%1,%2,%3};"
        : "+f"(d[0]), "+f"(d[1]), "+f"(d[2]), "+f"(d[3])
        : "r"(a[0]), "r"(a[1]), "r"(a[2]), "r"(a[3]), "r"(b0), "r"(b1));
}

// Zero-C variant: D = A*B + 0, writes acc without reading it.
// Replaces the 128-MOV acc zero-init (saves ~256 issue-cyc/warp-eval).
static __device__ __forceinline__ void mma16z(float* d, const uint32_t* a,
                                              uint32_t b0, uint32_t b1) {
    const float z = 0.0f;
    asm volatile(
        "mma.sync.aligned.m16n8k16.row.col.f32.f16.f16.f32 "
        "{%0,%1,%2,%3}, {%4,%5,%6,%7}, {%8,%9}, {%10,%10,%10,%10};"
        : "=f"(d[0]), "=f"(d[1]), "=f"(d[2]), "=f"(d[3])
        : "r"(a[0]), "r"(a[1]), "r"(a[2]), "r"(a[3]), "r"(b0), "r"(b1), "f"(z));
}

// One SIREN vector-field eval for this warp's 32 points (lane l owns point l).
// R9 structure (the measured optimum): single pass, 32 independent depth-8
// MMA chains, layer-1 sins inside the kt loop. kt=0 peeled with zero-C MMAs.
__device__ __noinline__ void feval(float px, float py, const char* sm,
                                   int lane, float b3x, float b3y,
                                   float& fx, float& fy) {
    const int g = lane >> 2, tig = lane & 3;

    // coords of the 4 rows (8j+g) whose fragment slots this lane owns
    float rx[4], ry[4];
#pragma unroll
    for (int j = 0; j < 4; j++) {
        rx[j] = __shfl_sync(0xffffffffu, px, 8 * j + g);
        ry[j] = __shfl_sync(0xffffffffu, py, 8 * j + g);
    }

    float acc[128];
    const float4* P1 = reinterpret_cast<const float4*>(sm + P1_OFF);
    const uint4* BF = reinterpret_cast<const uint4*>(sm + BF_OFF);

#pragma unroll
    for (int kt = 0; kt < 8; kt++) {
        const int c0 = 16 * kt + 2 * tig;
        float4 pA = P1[c0], pB = P1[c0 + 1], pC = P1[c0 + 8], pD = P1[c0 + 9];

        // A fragments: rows 8j+g, k-cols {c0,c0+1} (low pair), {c0+8,c0+9}
        uint32_t ah[8];
#pragma unroll
        for (int j = 0; j < 4; j++) {
            float sA = __sinf(fmaf(rx[j], pA.x, fmaf(ry[j], pA.y, pA.z)));
            float sB = __sinf(fmaf(rx[j], pB.x, fmaf(ry[j], pB.y, pB.z)));
            float sC = __sinf(fmaf(rx[j], pC.x, fmaf(ry[j], pC.y, pC.z)));
            float sD = __sinf(fmaf(rx[j], pD.x, fmaf(ry[j], pD.y, pD.z)));
            const int m = j >> 1, rs = j & 1;
            ah[m * 4 + rs]     = h2(sA, sB);   // low-k pair
            ah[m * 4 + rs + 2] = h2(sC, sD);   // high-k pair
        }

        const uint4* Bk = BF + kt * 256;
        if (kt == 0) {
#pragma unroll
            for (int ntp = 0; ntp < 8; ntp++) {
                uint4 b = Bk[ntp * 32 + g * 4 + tig];
                mma16z(acc + (2 * ntp) * 4,          ah,     b.x, b.y);
                mma16z(acc + 64 + (2 * ntp) * 4,     ah + 4, b.x, b.y);
                mma16z(acc + (2 * ntp + 1) * 4,      ah,     b.z, b.w);
                mma16z(acc + 64 + (2 * ntp + 1) * 4, ah + 4, b.z, b.w);
            }
        } else {
#pragma unroll
            for (int ntp = 0; ntp < 8; ntp++) {
                uint4 b = Bk[ntp * 32 + g * 4 + tig];
                mma16(acc + (2 * ntp) * 4,          ah,     b.x, b.y);
                mma16(acc + 64 + (2 * ntp) * 4,     ah + 4, b.x, b.y);
                mma16(acc + (2 * ntp + 1) * 4,      ah,     b.z, b.w);
                mma16(acc + 64 + (2 * ntp + 1) * 4, ah + 4, b.z, b.w);
            }
        }
    }

    // ---- layer 3: f = sin(44*D + 44*b2) @ W3 + b3 ----
    const float4* WB = reinterpret_cast<const float4*>(sm + WB_OFF);
    float ps[8];
#pragma unroll
    for (int i = 0; i < 8; i++) ps[i] = 0.0f;
#pragma unroll
    for (int m = 0; m < 2; m++) {
#pragma unroll
        for (int nt = 0; nt < 16; nt++) {
            float4 w0 = WB[8 * nt + 2 * tig];
            float4 w1 = WB[8 * nt + 2 * tig + 1];
            const float* d = acc + m * 64 + nt * 4;
            float h00 = __sinf(fmaf(W0F, d[0], w0.z));  // row g,   col 2tig
            float h01 = __sinf(fmaf(W0F, d[1], w1.z));  // row g,   col 2tig+1
            float h10 = __sinf(fmaf(W0F, d[2], w0.z));  // row g+8
            float h11 = __sinf(fmaf(W0F, d[3], w1.z));
            ps[m * 4 + 0] = fmaf(h00, w0.x, fmaf(h01, w1.x, ps[m * 4 + 0]));
            ps[m * 4 + 1] = fmaf(h00, w0.y, fmaf(h01, w1.y, ps[m * 4 + 1]));
            ps[m * 4 + 2] = fmaf(h10, w0.x, fmaf(h11, w1.x, ps[m * 4 + 2]));
            ps[m * 4 + 3] = fmaf(h10, w0.y, fmaf(h11, w1.y, ps[m * 4 + 3]));
        }
    }
    // reduce across the 4 lanes of each thread-group (lane bits 0,1)
#pragma unroll
    for (int d = 1; d <= 2; d <<= 1)
#pragma unroll
        for (int i = 0; i < 8; i++)
            ps[i] += __shfl_xor_sync(0xffffffffu, ps[i], d);

    // route row r = 8*s + g back to owner lane r (src lane = (r&7)*4);
    // ps index = 2*s + comp where s = 2m+h, row = 8s+g
    const int src = (lane & 7) * 4;
    float rx0 = __shfl_sync(0xffffffffu, ps[0], src);
    float ry0 = __shfl_sync(0xffffffffu, ps[1], src);
    float rx1 = __shfl_sync(0xffffffffu, ps[2], src);
    float ry1 = __shfl_sync(0xffffffffu, ps[3], src);
    float rx2 = __shfl_sync(0xffffffffu, ps[4], src);
    float ry2 = __shfl_sync(0xffffffffu, ps[5], src);
    float rx3 = __shfl_sync(0xffffffffu, ps[6], src);
    float ry3 = __shfl_sync(0xffffffffu, ps[7], src);
    const int s = lane >> 3;
    fx = b3x + ((s == 0) ? rx0 : (s == 1) ? rx1 : (s == 2) ? rx2 : rx3);
    fy = b3y + ((s == 0) ? ry0 : (s == 1) ? ry1 : (s == 2) ? ry2 : ry3);
}

extern "C" __global__ void __launch_bounds__(NTHR, 1)
node_hmma(const float* __restrict__ t, const float* __restrict__ x0,
          const float* __restrict__ W1, const float* __restrict__ b1,
          const float* __restrict__ W2, const float* __restrict__ b2,
          const float* __restrict__ W3, const float* __restrict__ b3g,
          float* __restrict__ out, int N) {
    extern __shared__ char sm[];
    const int tid = threadIdx.x;
    const int lane = tid & 31;

    // ---- stage W2 as f16 fragment uint4s: [kt][ntp][g][tig] ----
    // .x/.y = B-frag (b0,b1) for n0 = 16ntp+g; .z/.w = same for n1 = n0+8
    for (int idx = tid; idx < 8 * 8 * 32; idx += NTHR) {
        int tg = idx & 3, g = (idx >> 2) & 7, ntp = (idx >> 5) & 7, kt = idx >> 8;
        int n0 = 16 * ntp + g, n1 = n0 + 8;
        int k0 = 16 * kt + 2 * tg;
        uint4 v;
        v.x = h2(W2[k0 * 128 + n0],       W2[(k0 + 1) * 128 + n0]);
        v.y = h2(W2[(k0 + 8) * 128 + n0], W2[(k0 + 9) * 128 + n0]);
        v.z = h2(W2[k0 * 128 + n1],       W2[(k0 + 1) * 128 + n1]);
        v.w = h2(W2[(k0 + 8) * 128 + n1], W2[(k0 + 9) * 128 + n1]);
        reinterpret_cast<uint4*>(sm + BF_OFF)[idx] = v;
    }
    for (int k = tid; k < 128; k += NTHR) {
        reinterpret_cast<float4*>(sm + P1_OFF)[k] =
            make_float4(W0F * W1[k], W0F * W1[128 + k], W0F * b1[k], 0.0f);
        reinterpret_cast<float4*>(sm + WB_OFF)[k] =
            make_float4(W3[2 * k], W3[2 * k + 1], W0F * b2[k], 0.0f);
    }
    for (int s = tid; s < TT - 1; s += NTHR)
        reinterpret_cast<float*>(sm + DTS_OFF)[s] = t[s + 1] - t[s];
    if (tid < 2) reinterpret_cast<float*>(sm + B3_OFF)[tid] = b3g[tid];
    __syncthreads();  // only CTA-wide sync; warps independent afterwards

    const float b3x = reinterpret_cast<const float*>(sm + B3_OFF)[0];
    const float b3y = reinterpret_cast<const float*>(sm + B3_OFF)[1];

    const int gid = blockIdx.x * NTHR + tid;
    const bool live = gid < N;
    float2 y = live ? reinterpret_cast<const float2*>(x0)[gid]
                    : make_float2(0.0f, 0.0f);
    float2* outv = reinterpret_cast<float2*>(out);
    if (live) outv[gid] = y;  // t = 0 row

    const float third = 1.0f / 3.0f;
#pragma unroll 1
    for (int s = 0; s < TT - 1; s++) {
        float dt = reinterpret_cast<const float*>(sm + DTS_OFF)[s];
        float k1x, k1y, k2x, k2y, k3x, k3y, k4x, k4y;
        // torchdiffeq rk4_alt (3/8-rule)
        feval(y.x, y.y, sm, lane, b3x, b3y, k1x, k1y);
        feval(y.x + dt * k1x * third, y.y + dt * k1y * third,
              sm, lane, b3x, b3y, k2x, k2y);
        feval(y.x + dt * (k2x - k1x * third), y.y + dt * (k2y - k1y * third),
              sm, lane, b3x, b3y, k3x, k3y);
        feval(y.x + dt * (k1x - k2x + k3x), y.y + dt * (k1y - k2y + k3y),
              sm, lane, b3x, b3y, k4x, k4y);
        y.x = y.x + (k1x + 3.0f * (k2x + k3x) + k4x) * dt * 0.125f;
        y.y = y.y + (k1y + 3.0f * (k2y + k3y) + k4y) * dt * 0.125f;
        if (live) outv[(size_t)(s + 1) * N + gid] = y;
    }
}

extern "C" void kernel_launch(void* const* d_in, const int* in_sizes, int n_in,
                              void* d_out, int out_size) {
    const float* t  = (const float*)d_in[0];
    const float* x0 = (const float*)d_in[1];
    const float* W1 = (const float*)d_in[2];
    const float* b1 = (const float*)d_in[3];
    const float* W2 = (const float*)d_in[4];
    const float* b2 = (const float*)d_in[5];
    const float* W3 = (const float*)d_in[6];
    const float* b3 = (const float*)d_in[7];
    int N = in_sizes[1] / 2;

    cudaFuncSetAttribute(node_hmma,
                         cudaFuncAttributeMaxDynamicSharedMemorySize, SMEM_TOTAL);
    int grid = (N + NTHR - 1) / NTHR;
    node_hmma<<<grid, NTHR, SMEM_TOTAL>>>(t, x0, W1, b1, W2, b2, W3, b3,
                                          (float*)d_out, N);
}